// round 4
// baseline (speedup 1.0000x reference)
#include <cuda_runtime.h>
#include <cuda_fp16.h>
#include <cstdint>

#define V_CONST 163842
#define CIN 64
#define COUT 64
#define TILE_M 256
#define NTHREADS 256
#define NTILES ((V_CONST + TILE_M - 1) / TILE_M)   // 641
#define MAX_B 2

// ---- persistent device scratch ----
__device__ uint4 gx4[(size_t)MAX_B * V_CONST * CIN / 8];   // x as fp16, row-linear (128B rows)
__device__ uint4 gw4[7 * 64 * 64 / 8];                     // W as fp16, pre-swizzled per j (8KB blocks)

// ---- shared memory layout: 128B-pitch rows, 16B-unit XOR swizzle ----
#define XH_OFF 0             // 256 rows x 128B = 32KB
#define WH_OFF 32768         // 64 rows x 128B = 8KB
#define BUF_BYTES 40960
#define OFF_BIAS (2 * BUF_BYTES)               // 81920
#define SMEM_TOTAL (OFF_BIAS + 256 + 64)

// ---------------- helpers ----------------
__device__ __forceinline__ uint32_t smem_u32(const void* p) {
    uint32_t a;
    asm("{ .reg .u64 t; cvta.to.shared.u64 t, %1; cvt.u32.u64 %0, t; }" : "=r"(a) : "l"(p));
    return a;
}
__device__ __forceinline__ void cpasync16(uint32_t dst, const void* src) {
    asm volatile("cp.async.cg.shared.global [%0], [%1], 16;" :: "r"(dst), "l"(src) : "memory");
}
__device__ __forceinline__ void ldmx4(uint32_t* a, uint32_t addr) {
    asm volatile("ldmatrix.sync.aligned.m8n8.x4.shared.b16 {%0,%1,%2,%3}, [%4];"
                 : "=r"(a[0]), "=r"(a[1]), "=r"(a[2]), "=r"(a[3]) : "r"(addr));
}
__device__ __forceinline__ void ldmx2(uint32_t* b, uint32_t addr) {
    asm volatile("ldmatrix.sync.aligned.m8n8.x2.shared.b16 {%0,%1}, [%2];"
                 : "=r"(b[0]), "=r"(b[1]) : "r"(addr));
}
__device__ __forceinline__ void mma16816(float* d, const uint32_t* a, const uint32_t* b) {
    asm volatile(
        "mma.sync.aligned.m16n8k16.row.col.f32.f16.f16.f32 "
        "{%0,%1,%2,%3}, {%4,%5,%6,%7}, {%8,%9}, {%0,%1,%2,%3};"
        : "+f"(d[0]), "+f"(d[1]), "+f"(d[2]), "+f"(d[3])
        : "r"(a[0]), "r"(a[1]), "r"(a[2]), "r"(a[3]), "r"(b[0]), "r"(b[1]));
}
__device__ __forceinline__ uint32_t packh2(float a, float b) {
    __half2 h = __floats2half2_rn(a, b);
    return *reinterpret_cast<uint32_t*>(&h);
}

// ---------------- pre-pass: x fp32 -> fp16 (row-linear); W fp32 -> fp16 pre-swizzled ----------------
__global__ void prep_kernel(const float* __restrict__ x, const float* __restrict__ Wg,
                            size_t total8, unsigned xblocks) {
    if (blockIdx.x < xblocks) {
        size_t i = (size_t)blockIdx.x * blockDim.x + threadIdx.x;   // one 8-float chunk
        if (i >= total8) return;
        const float4* s = (const float4*)(x + i * 8);
        float4 a = s[0], b = s[1];
        uint4 o;
        o.x = packh2(a.x, a.y); o.y = packh2(a.z, a.w);
        o.z = packh2(b.x, b.y); o.w = packh2(b.z, b.w);
        gx4[i] = o;
    } else {
        const int j = blockIdx.x - xblocks;    // 0..6
        const int tid = threadIdx.x;           // 256
        #pragma unroll
        for (int t = 0; t < 2; t++) {
            const int c = tid * 2 + t;         // chunk 0..511
            const int o = c >> 3;              // out row 0..63
            const int u = c & 7;               // 16B chunk within row
            const float* s = Wg + (size_t)o * (7 * CIN) + j * CIN + u * 8;
            uint4 v;
            v.x = packh2(s[0], s[1]); v.y = packh2(s[2], s[3]);
            v.z = packh2(s[4], s[5]); v.w = packh2(s[6], s[7]);
            const uint32_t dst = (uint32_t)j * 8192 + (uint32_t)o * 128 + (uint32_t)((u ^ (o & 7)) << 4);
            *(uint4*)((char*)gw4 + dst) = v;
        }
    }
}

// ---------------- main kernel ----------------
__global__ __launch_bounds__(NTHREADS, 2)
void conv_layer_kernel(const void* __restrict__ neigh,
                       const float* __restrict__ bias,
                       float* __restrict__ out)
{
    extern __shared__ char smem[];
    const uint32_t sb = smem_u32(smem);
    const int tid  = threadIdx.x;
    const int wid  = tid >> 5;
    const int lane = tid & 31;
    const int batch = blockIdx.y;
    const long long v0 = (long long)blockIdx.x * TILE_M;

    // detect int64 vs int32 neigh_orders
    uint32_t hiacc = 0;
    {
        const uint2* p = (const uint2*)neigh;
        #pragma unroll
        for (int i = 0; i < 8; i++) hiacc |= p[i].y;
    }
    const bool is64 = (hiacc == 0);

    if (tid < COUT) ((float*)(smem + OFF_BIAS))[tid] = bias[tid];

    // gather mapping: one thread = one full 128B fp16 row (8 x 16B cp.async)
    const int r = tid;
    long long vv = v0 + r;
    if (vv >= V_CONST) vv = V_CONST - 1;
    const size_t neigh_base = (size_t)vv * 7;
    const char* gxb = (const char*)gx4 + (size_t)batch * V_CONST * 128;

    auto issue = [&](int jj, int buf) {
        long long u = is64 ? ((const long long*)neigh)[neigh_base + jj]
                           : (long long)((const int*)neigh)[neigh_base + jj];
        if (u < 0) u = 0;
        if (u >= V_CONST) u = V_CONST - 1;
        const char* src = gxb + (size_t)u * 128;
        const uint32_t xB = sb + buf * BUF_BYTES + XH_OFF + (uint32_t)r * 128;
        const int rs = r & 7;
        #pragma unroll
        for (int q = 0; q < 8; q++)
            cpasync16(xB + (((uint32_t)q ^ rs) << 4), src + q * 16);
        // W block jj: 8KB pre-swizzled, linear copy (2 x 16B per thread)
        const char* wsrc = (const char*)gw4 + (size_t)jj * 8192 + (size_t)tid * 32;
        const uint32_t wdst = sb + buf * BUF_BYTES + WH_OFF + (uint32_t)tid * 32;
        cpasync16(wdst, wsrc);
        cpasync16(wdst + 16, wsrc + 16);
        asm volatile("cp.async.commit_group;" ::: "memory");
    };

    float acc[4][4][4];
    #pragma unroll
    for (int mt = 0; mt < 4; mt++)
        #pragma unroll
        for (int n = 0; n < 4; n++)
            #pragma unroll
            for (int q = 0; q < 4; q++) acc[mt][n][q] = 0.0f;

    // warp tiling: 4 M-groups (Mw=64) x 2 N-groups (Nw=32)
    const int mg = wid & 3;
    const int ng = wid >> 2;
    const int acol = (lane >> 4);
    const int blane = lane & 7;
    const int bsel = (lane >> 3) & 1;

    issue(0, 0);

    for (int j = 0; j < 7; j++) {
        const int buf = j & 1;
        if (j < 6) issue(j + 1, buf ^ 1);

        if (j < 6) asm volatile("cp.async.wait_group 1;" ::: "memory");
        else       asm volatile("cp.async.wait_group 0;" ::: "memory");
        __syncthreads();

        const uint32_t xhB = sb + buf * BUF_BYTES + XH_OFF;
        const uint32_t whB = sb + buf * BUF_BYTES + WH_OFF;

        #pragma unroll
        for (int k = 0; k < 4; k++) {
            uint32_t bfr[4][2];
            #pragma unroll
            for (int n = 0; n < 4; n++) {
                const int br = ng * 32 + n * 8 + blane;
                const uint32_t uc = (uint32_t)(2 * k + bsel);
                ldmx2(bfr[n], whB + (uint32_t)br * 128 + ((uc ^ (br & 7)) << 4));
            }
            #pragma unroll
            for (int mt = 0; mt < 4; mt++) {
                uint32_t afr[4];
                const int ar = mg * 64 + mt * 16 + (lane & 15);
                const uint32_t uc = (uint32_t)(2 * k + acol);
                ldmx4(afr, xhB + (uint32_t)ar * 128 + ((uc ^ (ar & 7)) << 4));
                #pragma unroll
                for (int n = 0; n < 4; n++)
                    mma16816(acc[mt][n], afr, bfr[n]);
            }
        }
        __syncthreads();   // all reads of buf done before next iteration overwrites it
    }

    // ---------------- epilogue ----------------
    {
        const float* bs = (const float*)(smem + OFF_BIAS);
        const size_t obase = (size_t)batch * V_CONST * COUT;
        #pragma unroll
        for (int mt = 0; mt < 4; mt++) {
            const long long row0 = v0 + mg * 64 + mt * 16 + (lane >> 2);
            #pragma unroll
            for (int n = 0; n < 4; n++) {
                const int c = ng * 32 + n * 8 + (lane & 3) * 2;
                const float b0 = bs[c], b1 = bs[c + 1];
                if (row0 < V_CONST) {
                    float2 v; v.x = acc[mt][n][0] + b0; v.y = acc[mt][n][1] + b1;
                    *(float2*)(out + obase + (size_t)row0 * COUT + c) = v;
                }
                if (row0 + 8 < V_CONST) {
                    float2 v; v.x = acc[mt][n][2] + b0; v.y = acc[mt][n][3] + b1;
                    *(float2*)(out + obase + (size_t)(row0 + 8) * COUT + c) = v;
                }
            }
        }
    }
}

// ---------------- launch ----------------
extern "C" void kernel_launch(void* const* d_in, const int* in_sizes, int n_in,
                              void* d_out, int out_size) {
    const float* x     = (const float*)d_in[0];
    const void*  neigh = d_in[1];
    const float* Wg    = (const float*)d_in[2];
    const float* b     = (const float*)d_in[3];
    float* out = (float*)d_out;

    const int B = in_sizes[0] / (V_CONST * CIN);   // = 2

    const size_t total8 = (size_t)B * V_CONST * CIN / 8;
    const unsigned xblocks = (unsigned)((total8 + 255) / 256);
    prep_kernel<<<xblocks + 7, 256>>>(x, Wg, total8, xblocks);

    cudaFuncSetAttribute(conv_layer_kernel,
                         cudaFuncAttributeMaxDynamicSharedMemorySize, SMEM_TOTAL);
    dim3 grid(NTILES, B);
    conv_layer_kernel<<<grid, NTHREADS, SMEM_TOTAL>>>(neigh, b, out);
}

// round 5
// speedup vs baseline: 1.4303x; 1.4303x over previous
#include <cuda_runtime.h>
#include <cuda_fp16.h>
#include <cstdint>

#define V_CONST 163842
#define CIN 64
#define COUT 64
#define TILE_M 128
#define NTHREADS 256
#define NTILES ((V_CONST + TILE_M - 1) / TILE_M)   // 1281
#define MAX_B 2

// ---- persistent device scratch ----
__device__ uint4 gx4[(size_t)MAX_B * V_CONST * CIN / 8];   // x as fp16, row-linear (128B rows)
__device__ uint4 gw4[7 * 64 * 64 / 8];                     // W as fp16, pre-swizzled per j (8KB blocks)

// ---- shared memory: 3 buffers, 128B-pitch rows, 16B-unit XOR swizzle ----
#define XH_OFF 0             // 128 rows x 128B = 16KB
#define WH_OFF 16384         // 64 rows x 128B = 8KB
#define BUF_BYTES 24576
#define NBUF 3
#define OFF_BIAS (NBUF * BUF_BYTES)            // 73728
#define SMEM_TOTAL (OFF_BIAS + 256 + 64)

// ---------------- helpers ----------------
__device__ __forceinline__ uint32_t smem_u32(const void* p) {
    uint32_t a;
    asm("{ .reg .u64 t; cvta.to.shared.u64 t, %1; cvt.u32.u64 %0, t; }" : "=r"(a) : "l"(p));
    return a;
}
__device__ __forceinline__ void cpasync16(uint32_t dst, const void* src) {
    asm volatile("cp.async.cg.shared.global [%0], [%1], 16;" :: "r"(dst), "l"(src) : "memory");
}
__device__ __forceinline__ void ldmx4(uint32_t* a, uint32_t addr) {
    asm volatile("ldmatrix.sync.aligned.m8n8.x4.shared.b16 {%0,%1,%2,%3}, [%4];"
                 : "=r"(a[0]), "=r"(a[1]), "=r"(a[2]), "=r"(a[3]) : "r"(addr));
}
__device__ __forceinline__ void mma16816(float* d, const uint32_t* a, const uint32_t* b) {
    asm volatile(
        "mma.sync.aligned.m16n8k16.row.col.f32.f16.f16.f32 "
        "{%0,%1,%2,%3}, {%4,%5,%6,%7}, {%8,%9}, {%0,%1,%2,%3};"
        : "+f"(d[0]), "+f"(d[1]), "+f"(d[2]), "+f"(d[3])
        : "r"(a[0]), "r"(a[1]), "r"(a[2]), "r"(a[3]), "r"(b[0]), "r"(b[1]));
}
__device__ __forceinline__ uint32_t packh2(float a, float b) {
    __half2 h = __floats2half2_rn(a, b);
    return *reinterpret_cast<uint32_t*>(&h);
}

// ---------------- pre-pass: x fp32 -> fp16 (row-linear); W fp32 -> fp16 pre-swizzled ----------------
__global__ void prep_kernel(const float* __restrict__ x, const float* __restrict__ Wg,
                            size_t total8, unsigned xblocks) {
    if (blockIdx.x < xblocks) {
        size_t i = (size_t)blockIdx.x * blockDim.x + threadIdx.x;
        if (i >= total8) return;
        const float4* s = (const float4*)(x + i * 8);
        float4 a = s[0], b = s[1];
        uint4 o;
        o.x = packh2(a.x, a.y); o.y = packh2(a.z, a.w);
        o.z = packh2(b.x, b.y); o.w = packh2(b.z, b.w);
        gx4[i] = o;
    } else {
        const int j = blockIdx.x - xblocks;    // 0..6
        const int tid = threadIdx.x;           // 256
        #pragma unroll
        for (int t = 0; t < 2; t++) {
            const int c = tid * 2 + t;         // chunk 0..511
            const int o = c >> 3;              // out row 0..63
            const int u = c & 7;               // 16B chunk within row
            const float* s = Wg + (size_t)o * (7 * CIN) + j * CIN + u * 8;
            uint4 v;
            v.x = packh2(s[0], s[1]); v.y = packh2(s[2], s[3]);
            v.z = packh2(s[4], s[5]); v.w = packh2(s[6], s[7]);
            const uint32_t dst = (uint32_t)j * 8192 + (uint32_t)o * 128 + (uint32_t)((u ^ (o & 7)) << 4);
            *(uint4*)((char*)gw4 + dst) = v;
        }
    }
}

// ---------------- main kernel ----------------
__global__ __launch_bounds__(NTHREADS, 3)
void conv_layer_kernel(const void* __restrict__ neigh,
                       const float* __restrict__ bias,
                       float* __restrict__ out)
{
    extern __shared__ char smem[];
    const uint32_t sb = smem_u32(smem);
    const int tid  = threadIdx.x;
    const int wid  = tid >> 5;
    const int lane = tid & 31;
    const int batch = blockIdx.y;
    const long long v0 = (long long)blockIdx.x * TILE_M;

    // detect int64 vs int32 neigh_orders
    uint32_t hiacc = 0;
    {
        const uint2* p = (const uint2*)neigh;
        #pragma unroll
        for (int i = 0; i < 8; i++) hiacc |= p[i].y;
    }
    const bool is64 = (hiacc == 0);

    if (tid < COUT) ((float*)(smem + OFF_BIAS))[tid] = bias[tid];

    // gather mapping: two threads per row, 4 x 16B cp.async each
    const int r = tid >> 1;
    const int h = tid & 1;
    long long vv = v0 + r;
    if (vv >= V_CONST) vv = V_CONST - 1;

    // preload all 7 neighbor indices (clamped)
    unsigned uidx[7];
    {
        const size_t nb = (size_t)vv * 7;
        #pragma unroll
        for (int j = 0; j < 7; j++) {
            long long u = is64 ? ((const long long*)neigh)[nb + j]
                               : (long long)((const int*)neigh)[nb + j];
            if (u < 0) u = 0;
            if (u >= V_CONST) u = V_CONST - 1;
            uidx[j] = (unsigned)u;
        }
    }
    const char* gxb = (const char*)gx4 + (size_t)batch * V_CONST * 128;

    auto issue = [&](int jj, int buf) {
        const char* src = gxb + (size_t)uidx[jj] * 128 + h * 64;
        const uint32_t xB = sb + buf * BUF_BYTES + XH_OFF + (uint32_t)r * 128;
        const int rs = r & 7;
        #pragma unroll
        for (int q = 0; q < 4; q++) {
            const uint32_t uc = (uint32_t)(h * 4 + q);
            cpasync16(xB + ((uc ^ rs) << 4), src + q * 16);
        }
        // W block jj: 8KB pre-swizzled, linear copy (2 x 16B per thread)
        const char* wsrc = (const char*)gw4 + (size_t)jj * 8192 + (size_t)tid * 32;
        const uint32_t wdst = sb + buf * BUF_BYTES + WH_OFF + (uint32_t)tid * 32;
        cpasync16(wdst, wsrc);
        cpasync16(wdst + 16, wsrc + 16);
        asm volatile("cp.async.commit_group;" ::: "memory");
    };

    float acc[2][4][4];
    #pragma unroll
    for (int mt = 0; mt < 2; mt++)
        #pragma unroll
        for (int n = 0; n < 4; n++)
            #pragma unroll
            for (int q = 0; q < 4; q++) acc[mt][n][q] = 0.0f;

    // warp tiling: 4 M-groups (Mw=32) x 2 N-groups (Nw=32)
    const int mg = wid & 3;
    const int ng = wid >> 2;
    const int acol = (lane >> 4);
    const int blane = lane & 7;
    const int bsel = (lane >> 3) & 1;
    const int bnt  = (lane >> 4);          // n-tile within pair for B x4 load

    issue(0, 0);

    for (int j = 0; j < 7; j++) {
        const int buf = j % NBUF;
        if (j < 6) issue(j + 1, (j + 1) % NBUF);

        if (j < 6) asm volatile("cp.async.wait_group 1;" ::: "memory");
        else       asm volatile("cp.async.wait_group 0;" ::: "memory");
        __syncthreads();   // single barrier per j (NBUF=3 covers WAR on reuse)

        const uint32_t xhB = sb + buf * BUF_BYTES + XH_OFF;
        const uint32_t whB = sb + buf * BUF_BYTES + WH_OFF;

        #pragma unroll
        for (int k = 0; k < 4; k++) {
            // B frags: 2 x ldmatrix.x4, each covers two n-tiles
            uint32_t bfr[4][2];
            #pragma unroll
            for (int np = 0; np < 2; np++) {
                const int br = ng * 32 + np * 16 + bnt * 8 + blane;
                const uint32_t uc = (uint32_t)(2 * k + bsel);
                uint32_t t4[4];
                ldmx4(t4, whB + (uint32_t)br * 128 + ((uc ^ (br & 7)) << 4));
                bfr[2 * np + 0][0] = t4[0]; bfr[2 * np + 0][1] = t4[1];
                bfr[2 * np + 1][0] = t4[2]; bfr[2 * np + 1][1] = t4[3];
            }
            // A frags: 2 x ldmatrix.x4 (two 16-row m-tiles)
            uint32_t afr[2][4];
            #pragma unroll
            for (int mt = 0; mt < 2; mt++) {
                const int ar = mg * 32 + mt * 16 + (lane & 15);
                const uint32_t uc = (uint32_t)(2 * k + acol);
                ldmx4(afr[mt], xhB + (uint32_t)ar * 128 + ((uc ^ (ar & 7)) << 4));
            }
            #pragma unroll
            for (int mt = 0; mt < 2; mt++)
                #pragma unroll
                for (int n = 0; n < 4; n++)
                    mma16816(acc[mt][n], afr[mt], bfr[n]);
        }
    }

    // ---------------- epilogue ----------------
    {
        const float* bs = (const float*)(smem + OFF_BIAS);
        const size_t obase = (size_t)batch * V_CONST * COUT;
        #pragma unroll
        for (int mt = 0; mt < 2; mt++) {
            const long long row0 = v0 + mg * 32 + mt * 16 + (lane >> 2);
            #pragma unroll
            for (int n = 0; n < 4; n++) {
                const int c = ng * 32 + n * 8 + (lane & 3) * 2;
                const float b0 = bs[c], b1 = bs[c + 1];
                if (row0 < V_CONST) {
                    float2 v; v.x = acc[mt][n][0] + b0; v.y = acc[mt][n][1] + b1;
                    *(float2*)(out + obase + (size_t)row0 * COUT + c) = v;
                }
                if (row0 + 8 < V_CONST) {
                    float2 v; v.x = acc[mt][n][2] + b0; v.y = acc[mt][n][3] + b1;
                    *(float2*)(out + obase + (size_t)(row0 + 8) * COUT + c) = v;
                }
            }
        }
    }
}

// ---------------- launch ----------------
extern "C" void kernel_launch(void* const* d_in, const int* in_sizes, int n_in,
                              void* d_out, int out_size) {
    const float* x     = (const float*)d_in[0];
    const void*  neigh = d_in[1];
    const float* Wg    = (const float*)d_in[2];
    const float* b     = (const float*)d_in[3];
    float* out = (float*)d_out;

    const int B = in_sizes[0] / (V_CONST * CIN);   // = 2

    const size_t total8 = (size_t)B * V_CONST * CIN / 8;
    const unsigned xblocks = (unsigned)((total8 + 255) / 256);
    prep_kernel<<<xblocks + 7, 256>>>(x, Wg, total8, xblocks);

    cudaFuncSetAttribute(conv_layer_kernel,
                         cudaFuncAttributeMaxDynamicSharedMemorySize, SMEM_TOTAL);
    dim3 grid(NTILES, B);
    conv_layer_kernel<<<grid, NTHREADS, SMEM_TOTAL>>>(neigh, b, out);
}